// round 14
// baseline (speedup 1.0000x reference)
#include <cuda_runtime.h>
#include <math.h>

// ---------------------------------------------------------------------------
// Scratch (device globals — no runtime allocation allowed)
// ---------------------------------------------------------------------------
#define BUF_ELEMS (4*16*512*512)   // 64 MB each
__device__ float g_bufA[BUF_ELEMS];
__device__ float g_bufB[BUF_ELEMS];
__device__ float g_stats[8192];    // per-layer (b,c) raw sum/sumsq
__device__ float g_seg[128];       // 32 segments x (3 channel sums + count)

__global__ void zerok(float* p, int n) {
    int i = blockIdx.x * blockDim.x + threadIdx.x;
    if (i < n) p[i] = 0.f;
}

__inline__ __device__ float warpSum(float v) {
    #pragma unroll
    for (int o = 16; o > 0; o >>= 1) v += __shfl_down_sync(0xffffffffu, v, o);
    return v;
}

// Build per-channel (mean, rstd) table in smem from raw sums (this block's b).
template<int CIN, int TPB>
__inline__ __device__ void buildMR(float* s_mr, const float* __restrict__ statsIn,
                                   int b, float inv_n, int t)
{
    for (int i = t; i < CIN; i += TPB) {
        float s  = statsIn[2 * (b * CIN + i)];
        float ss = statsIn[2 * (b * CIN + i) + 1];
        float m  = s * inv_n;
        float var = ss * inv_n - m * m;
        s_mr[2 * i]     = m;
        s_mr[2 * i + 1] = rsqrtf(fmaxf(var, 0.f) + 1e-5f);
    }
}

__inline__ __device__ float normMR(float v, const float* s_mr, int ci) {
    float y = (v - s_mr[2 * ci]) * s_mr[2 * ci + 1];
    return y > 0.f ? y : 0.f;
}

// ---------------------------------------------------------------------------
// 7x7 conv, reflect pad 3, stride 1 (layers 0 and 9). R5 geometry.
// ---------------------------------------------------------------------------
template<int CIN, int COUT, int COPT, int TILEY, int TILEX, int PXW,
         int ACT, int NORM, int STATS, int CB>
__global__ void __launch_bounds__(256) conv7k(
    const float* __restrict__ in, const float* __restrict__ w,
    const float* __restrict__ bias, float* __restrict__ out,
    const float* __restrict__ statsIn, float* statsOut, float inv_n,
    int H, int W)
{
    constexpr int CG  = COUT / COPT;
    constexpr int PXT = 256 / CG;
    constexpr int TX  = TILEX / PXW;
    constexpr int TY  = TILEY / 2;
    static_assert(TX * TY == PXT, "thread grid mismatch");
    constexpr int ITY = TILEY + 6, ITX = TILEX + 6;
    constexpr int STR = (ITX % 2 == 0) ? ITX + 1 : ITX;
    constexpr int NPP = 2 * PXW;
    constexpr int SS  = STATS ? 2 * COUT : 1;
    constexpr int SMR = NORM ? 2 * CIN : 1;

    __shared__ float wsm[COUT * CIN * 49];
    __shared__ float s_in[CB * ITY * STR];
    __shared__ float sstat[SS];
    __shared__ float s_mr[SMR];

    const int t   = threadIdx.x;
    const int cog = t / PXT;
    const int pt  = t % PXT;
    const int ptx = pt % TX, pty = pt / TX;
    const int b   = blockIdx.z;
    const int by  = blockIdx.y * TILEY, bx = blockIdx.x * TILEX;

    for (int i = t; i < COUT * CIN * 49; i += 256) wsm[i] = w[i];
    if (STATS) for (int i = t; i < 2 * COUT; i += 256) sstat[i] = 0.f;
    if (NORM)  buildMR<CIN, 256>(s_mr, statsIn, b, inv_n, t);

    float acc[COPT][NPP];
    #pragma unroll
    for (int o = 0; o < COPT; o++)
        #pragma unroll
        for (int p = 0; p < NPP; p++) acc[o][p] = 0.f;

    for (int ci0 = 0; ci0 < CIN; ci0 += CB) {
        __syncthreads();
        for (int i = t; i < CB * ITY * ITX; i += 256) {
            int ciL = i / (ITY * ITX);
            int rr  = i % (ITY * ITX);
            int r = rr / ITX, c = rr % ITX;
            int gy = by + r - 3; gy = gy < 0 ? -gy : gy; gy = gy >= H ? 2 * H - 2 - gy : gy;
            int gx = bx + c - 3; gx = gx < 0 ? -gx : gx; gx = gx >= W ? 2 * W - 2 - gx : gx;
            int ci = ci0 + ciL;
            float v = in[((b * CIN + ci) * H + gy) * W + gx];
            if (NORM) v = normMR(v, s_mr, ci);
            s_in[(ciL * ITY + r) * STR + c] = v;
        }
        __syncthreads();
        for (int ciL = 0; ciL < CB; ciL++) {
            const int ci = ci0 + ciL;
            #pragma unroll
            for (int ky = 0; ky < 7; ky++) {
                #pragma unroll
                for (int kx = 0; kx < 7; kx++) {
                    float wr[COPT];
                    #pragma unroll
                    for (int o = 0; o < COPT; o++)
                        wr[o] = wsm[((cog * COPT + o) * CIN + ci) * 49 + ky * 7 + kx];
                    #pragma unroll
                    for (int dy = 0; dy < 2; dy++) {
                        #pragma unroll
                        for (int dx = 0; dx < PXW; dx++) {
                            float v = s_in[(ciL * ITY + (2 * pty + dy + ky)) * STR
                                           + (PXW * ptx + dx + kx)];
                            #pragma unroll
                            for (int o = 0; o < COPT; o++)
                                acc[o][dy * PXW + dx] += v * wr[o];
                        }
                    }
                }
            }
        }
    }

    #pragma unroll
    for (int o = 0; o < COPT; o++) {
        int co = cog * COPT + o;
        float bb = bias[co];
        float s = 0.f, ssq = 0.f;
        #pragma unroll
        for (int p = 0; p < NPP; p++) {
            float v = acc[o][p] + bb;
            if (STATS) { s += v; ssq += v * v; }
            int py = p / PXW, pxc = p % PXW;
            int y = by + 2 * pty + py, x = bx + PXW * ptx + pxc;
            float ov = (ACT == 1) ? tanhf(v) : v;
            out[((b * COUT + co) * H + y) * W + x] = ov;
        }
        if (STATS) {
            s = warpSum(s); ssq = warpSum(ssq);
            if ((t & 31) == 0) {
                atomicAdd(&sstat[2 * co], s);
                atomicAdd(&sstat[2 * co + 1], ssq);
            }
        }
    }
    if (STATS) {
        __syncthreads();
        for (int i = t; i < 2 * COUT; i += 256)
            atomicAdd(&statsOut[2 * b * COUT + i], sstat[i]);
    }
}

// ---------------------------------------------------------------------------
// 3x3 stride-2 pad-1 conv, 2 co/thread, row-vectorized, per-ky weights.
// Weight smem: PADDED TRANSPOSE wsm[r * (COUT+1) + co], r = ciL*9+k.
//  - loader reads gmem contiguously (r innermost within each co run)
//  - scatter-store stride COUT+1 (odd) -> conflict-free STS
//  - compute reads across warp cp at stride 2 -> conflict-free LDS
// ---------------------------------------------------------------------------
template<int CIN, int COUT, int TPB, int TP, int CB, int NORM, int STATS>
__global__ void __launch_bounds__(TPB) conv3s2k(
    const float* __restrict__ in, const float* __restrict__ w,
    const float* __restrict__ bias, float* __restrict__ out,
    const float* __restrict__ statsIn, float* statsOut, float inv_n,
    int Hin, int Win)
{
    constexpr int CP   = COUT / 2;
    constexpr int G    = TPB / CP;
    constexpr int NPIX = TP * TP;
    constexpr int PX   = NPIX / G;
    static_assert(PX >= 1 && PX % TP == 0, "threads must own whole rows");
    constexpr int NROWS = PX / TP;
    constexpr int IW   = 2 * TP + 1;
    constexpr int SW   = ((IW + 3) / 4) * 4;   // 16B-aligned row stride
    constexpr int SS   = STATS ? 2 * COUT : 1;
    constexpr int SMR  = NORM ? 2 * CIN : 1;
    constexpr int WPC  = CB * 9;
    constexpr int WST  = COUT + 1;             // odd stride

    __shared__ float wsm[WPC * WST];
    __shared__ __align__(16) float s_in[CB * IW * SW];
    __shared__ float sstat[SS];
    __shared__ float s_mr[SMR];

    const int t   = threadIdx.x;
    const int cp  = t % CP, g = t / CP;
    const int co0 = cp * 2;
    const int b   = blockIdx.z;
    const int oy0 = blockIdx.y * TP, ox0 = blockIdx.x * TP;
    const int Hout = Hin >> 1, Wout = Win >> 1;

    if (STATS) for (int i = t; i < 2 * COUT; i += TPB) sstat[i] = 0.f;
    if (NORM)  buildMR<CIN, TPB>(s_mr, statsIn, b, inv_n, t);

    float a0[PX], a1[PX];
    #pragma unroll
    for (int p = 0; p < PX; p++) { a0[p] = 0.f; a1[p] = 0.f; }

    for (int ci0 = 0; ci0 < CIN; ci0 += CB) {
        __syncthreads();
        // Weights: gmem-contiguous per co (r innermost), transpose into smem.
        for (int i = t; i < COUT * WPC; i += TPB) {
            int co = i / WPC;
            int r  = i % WPC;           // r = ciL*9 + k
            wsm[r * WST + co] = w[co * CIN * 9 + ci0 * 9 + r];
        }
        for (int i = t; i < CB * IW * IW; i += TPB) {
            int ciL = i / (IW * IW);
            int rr  = i % (IW * IW);
            int r = rr / IW, c = rr % IW;
            int gy = 2 * oy0 - 1 + r, gx = 2 * ox0 - 1 + c;
            float v = 0.f;
            if (gy >= 0 && gy < Hin && gx >= 0 && gx < Win) {
                int ci = ci0 + ciL;
                v = in[((b * CIN + ci) * Hin + gy) * Win + gx];
                if (NORM) v = normMR(v, s_mr, ci);
            }
            s_in[(ciL * IW + r) * SW + c] = v;
        }
        __syncthreads();
        for (int ciL = 0; ciL < CB; ciL++) {
            const float* wbase = &wsm[(ciL * 9) * WST + co0];
            #pragma unroll
            for (int rloc = 0; rloc < NROWS; rloc++) {
                const int py = g * NROWS + rloc;
                #pragma unroll
                for (int ky = 0; ky < 3; ky++) {
                    float w00 = wbase[(ky * 3 + 0) * WST];
                    float w01 = wbase[(ky * 3 + 1) * WST];
                    float w02 = wbase[(ky * 3 + 2) * WST];
                    float w10 = wbase[(ky * 3 + 0) * WST + 1];
                    float w11 = wbase[(ky * 3 + 1) * WST + 1];
                    float w12 = wbase[(ky * 3 + 2) * WST + 1];
                    const int iy = 2 * py + ky;
                    const float* rowp = &s_in[(ciL * IW + iy) * SW];
                    float rv[2 * TP + 1];
                    #pragma unroll
                    for (int j = 0; j < (2 * TP) / 4; j++) {
                        float4 q = *reinterpret_cast<const float4*>(rowp + 4 * j);
                        rv[4 * j]     = q.x;
                        rv[4 * j + 1] = q.y;
                        rv[4 * j + 2] = q.z;
                        rv[4 * j + 3] = q.w;
                    }
                    rv[2 * TP] = rowp[2 * TP];
                    #pragma unroll
                    for (int pxx = 0; pxx < TP; pxx++) {
                        float v0 = rv[2 * pxx];
                        float v1 = rv[2 * pxx + 1];
                        float v2 = rv[2 * pxx + 2];
                        a0[rloc * TP + pxx] += v0 * w00 + v1 * w01 + v2 * w02;
                        a1[rloc * TP + pxx] += v0 * w10 + v1 * w11 + v2 * w12;
                    }
                }
            }
        }
    }

    float b0v = bias[co0], b1v = bias[co0 + 1];
    float s0 = 0.f, ss0 = 0.f, s1 = 0.f, ss1 = 0.f;
    #pragma unroll
    for (int p = 0; p < PX; p++) {
        int pp = g * PX + p;
        int py = pp / TP, pxx = pp % TP;
        int oy = oy0 + py, ox = ox0 + pxx;
        float v0 = a0[p] + b0v, v1 = a1[p] + b1v;
        if (STATS) { s0 += v0; ss0 += v0 * v0; s1 += v1; ss1 += v1 * v1; }
        out[((b * COUT + co0) * Hout + oy) * Wout + ox]     = v0;
        out[((b * COUT + co0 + 1) * Hout + oy) * Wout + ox] = v1;
    }
    if (STATS) {
        atomicAdd(&sstat[2 * co0], s0);      atomicAdd(&sstat[2 * co0 + 1], ss0);
        atomicAdd(&sstat[2 * co0 + 2], s1);  atomicAdd(&sstat[2 * co0 + 3], ss1);
        __syncthreads();
        for (int i = t; i < 2 * COUT; i += TPB)
            atomicAdd(&statsOut[2 * b * COUT + i], sstat[i]);
    }
}

// ---------------------------------------------------------------------------
// ConvTranspose2d k=3 s=2 p=1 op=1, parity-specialized gather, 2 co/thread.
// Weight smem: padded transpose wsm[(ciL*9+k)*(COUT+1) + co]; loader reads
// gmem contiguously (w[ci0*COUT*9 + i]) and scatters. Conflict-free LDS/STS.
// ---------------------------------------------------------------------------
template<int CIN, int COUT, int TPB, int TP, int CB, int NORM, int STATS>
__global__ void __launch_bounds__(TPB) deconvk(
    const float* __restrict__ in, const float* __restrict__ w,
    const float* __restrict__ bias, float* __restrict__ out,
    const float* __restrict__ statsIn, float* statsOut, float inv_n,
    int Hin, int Win)
{
    constexpr int CP   = COUT / 2;
    constexpr int G    = TPB / CP;
    constexpr int HT   = TP / 2;
    constexpr int QP   = (TP * TP) / (4 * G);
    constexpr int PX   = 4 * QP;
    static_assert(QP >= 1, "tile too small");
    constexpr int IH   = HT + 1;
    constexpr int SW   = IH + 1;
    constexpr int SS   = STATS ? 2 * COUT : 1;
    constexpr int SMR  = NORM ? 2 * CIN : 1;
    constexpr int WST  = COUT + 1;

    __shared__ float wsm[CB * 9 * WST];
    __shared__ float s_in[CB * IH * SW];
    __shared__ float sstat[SS];
    __shared__ float s_mr[SMR];

    const int t   = threadIdx.x;
    const int cp  = t % CP, g = t / CP;
    const int co0 = cp * 2;
    const int b   = blockIdx.z;
    const int oy0 = blockIdx.y * TP, ox0 = blockIdx.x * TP;
    const int iy0 = oy0 >> 1, ix0 = ox0 >> 1;
    const int Hout = Hin * 2, Wout = Win * 2;

    if (STATS) for (int i = t; i < 2 * COUT; i += TPB) sstat[i] = 0.f;
    if (NORM)  buildMR<CIN, TPB>(s_mr, statsIn, b, inv_n, t);

    float a0[PX], a1[PX];
    #pragma unroll
    for (int p = 0; p < PX; p++) { a0[p] = 0.f; a1[p] = 0.f; }

    for (int ci0 = 0; ci0 < CIN; ci0 += CB) {
        __syncthreads();
        // gmem contiguous: i = ciL*(COUT*9) + co*9 + k
        for (int i = t; i < CB * COUT * 9; i += TPB) {
            int ciL = i / (COUT * 9);
            int rr  = i % (COUT * 9);
            int co  = rr / 9, k = rr % 9;
            wsm[(ciL * 9 + k) * WST + co] = w[ci0 * COUT * 9 + i];
        }
        for (int i = t; i < CB * IH * IH; i += TPB) {
            int ciL = i / (IH * IH);
            int rr  = i % (IH * IH);
            int r = rr / IH, c = rr % IH;
            int gy = iy0 + r, gx = ix0 + c;
            float v = 0.f;
            if (gy < Hin && gx < Win) {
                int ci = ci0 + ciL;
                v = in[((b * CIN + ci) * Hin + gy) * Win + gx];
                if (NORM) v = normMR(v, s_mr, ci);
            }
            s_in[(ciL * IH + r) * SW + c] = v;
        }
        __syncthreads();
        for (int ciL = 0; ciL < CB; ciL++) {
            const float* wbase = &wsm[(ciL * 9) * WST + co0];
            float w0[9], w1[9];
            #pragma unroll
            for (int k = 0; k < 9; k++) {
                w0[k] = wbase[k * WST];
                w1[k] = wbase[k * WST + 1];
            }
            const int rowB = ciL * IH;
            #pragma unroll
            for (int p = 0; p < PX; p++) {
                const int dyp = (p >> 1) & 1;   // compile-time after unroll
                const int dxp = p & 1;
                const int q   = g * QP + (p >> 2);
                const int qy  = q / HT, qx = q % HT;
                if (dyp == 0 && dxp == 0) {
                    float v = s_in[(rowB + qy) * SW + qx];
                    a0[p] += v * w0[4];
                    a1[p] += v * w1[4];
                } else if (dyp == 0) {
                    float va = s_in[(rowB + qy) * SW + qx + 1];
                    float vb = s_in[(rowB + qy) * SW + qx];
                    a0[p] += va * w0[3] + vb * w0[5];
                    a1[p] += va * w1[3] + vb * w1[5];
                } else if (dxp == 0) {
                    float va = s_in[(rowB + qy + 1) * SW + qx];
                    float vb = s_in[(rowB + qy) * SW + qx];
                    a0[p] += va * w0[1] + vb * w0[7];
                    a1[p] += va * w1[1] + vb * w1[7];
                } else {
                    float vaa = s_in[(rowB + qy + 1) * SW + qx + 1];
                    float vab = s_in[(rowB + qy + 1) * SW + qx];
                    float vba = s_in[(rowB + qy) * SW + qx + 1];
                    float vbb = s_in[(rowB + qy) * SW + qx];
                    a0[p] += vaa * w0[0] + vab * w0[2] + vba * w0[6] + vbb * w0[8];
                    a1[p] += vaa * w1[0] + vab * w1[2] + vba * w1[6] + vbb * w1[8];
                }
            }
        }
    }

    float b0v = bias[co0], b1v = bias[co0 + 1];
    float s0 = 0.f, ss0 = 0.f, s1 = 0.f, ss1 = 0.f;
    #pragma unroll
    for (int p = 0; p < PX; p++) {
        const int dyp = (p >> 1) & 1;
        const int dxp = p & 1;
        const int q   = g * QP + (p >> 2);
        const int qy  = q / HT, qx = q % HT;
        int oy = oy0 + 2 * qy + dyp, ox = ox0 + 2 * qx + dxp;
        float v0 = a0[p] + b0v, v1 = a1[p] + b1v;
        if (STATS) { s0 += v0; ss0 += v0 * v0; s1 += v1; ss1 += v1 * v1; }
        out[((b * COUT + co0) * Hout + oy) * Wout + ox]     = v0;
        out[((b * COUT + co0 + 1) * Hout + oy) * Wout + ox] = v1;
    }
    if (STATS) {
        atomicAdd(&sstat[2 * co0], s0);      atomicAdd(&sstat[2 * co0 + 1], ss0);
        atomicAdd(&sstat[2 * co0 + 2], s1);  atomicAdd(&sstat[2 * co0 + 3], ss1);
        __syncthreads();
        for (int i = t; i < 2 * COUT; i += TPB)
            atomicAdd(&statsOut[2 * b * COUT + i], sstat[i]);
    }
}

// ---------------------------------------------------------------------------
// Global segment mean over all B*H*W pixels, 32 segments, C=3.
// ---------------------------------------------------------------------------
__global__ void __launch_bounds__(256) seg_accum(
    const float* __restrict__ x, const int* __restrict__ inst,
    float* sums, int B, int HW)
{
    __shared__ float ls[128];
    if (threadIdx.x < 128) ls[threadIdx.x] = 0.f;
    __syncthreads();
    int total = B * HW;
    for (int i = blockIdx.x * blockDim.x + threadIdx.x; i < total;
         i += gridDim.x * blockDim.x) {
        int b = i / HW, px = i % HW;
        int s = inst[(size_t)b * HW + px];
        atomicAdd(&ls[s * 4 + 3], 1.0f);
        #pragma unroll
        for (int c = 0; c < 3; c++)
            atomicAdd(&ls[s * 4 + c], x[((size_t)(b * 3 + c)) * HW + px]);
    }
    __syncthreads();
    if (threadIdx.x < 128) atomicAdd(&sums[threadIdx.x], ls[threadIdx.x]);
}

// Scatter with on-the-fly mean (folds seg_final).
__global__ void seg_scatter(const float* __restrict__ sums,
                            const int* __restrict__ inst,
                            float* __restrict__ out, int B, int HW)
{
    int total = B * HW;
    for (int i = blockIdx.x * blockDim.x + threadIdx.x; i < total;
         i += gridDim.x * blockDim.x) {
        int b = i / HW, px = i % HW;
        int s = inst[(size_t)b * HW + px];
        float inv = 1.0f / fmaxf(sums[s * 4 + 3], 1.0f);
        #pragma unroll
        for (int c = 0; c < 3; c++)
            out[((size_t)(b * 3 + c)) * HW + px] = sums[s * 4 + c] * inv;
    }
}

// ---------------------------------------------------------------------------
// Launch (identical to R12/R13)
// ---------------------------------------------------------------------------
extern "C" void kernel_launch(void* const* d_in, const int* in_sizes, int n_in,
                              void* d_out, int out_size)
{
    (void)in_sizes; (void)n_in; (void)out_size;
    const float* input = (const float*)d_in[0];
    const int*   inst  = (const int*)d_in[1];
    const float* W[10]; const float* Bi[10];
    for (int i = 0; i < 10; i++) {
        W[i]  = (const float*)d_in[2 + 2 * i];
        Bi[i] = (const float*)d_in[3 + 2 * i];
    }
    float* out = (float*)d_out;

    float *dA, *dB, *dst, *dsg;
    cudaGetSymbolAddress((void**)&dA, g_bufA);
    cudaGetSymbolAddress((void**)&dB, g_bufB);
    cudaGetSymbolAddress((void**)&dst, g_stats);
    cudaGetSymbolAddress((void**)&dsg, g_seg);

    float* st0 = dst + 2 * 0;
    float* st1 = dst + 2 * 64;
    float* st2 = dst + 2 * 192;
    float* st3 = dst + 2 * 448;
    float* st4 = dst + 2 * 960;
    float* st5 = dst + 2 * 1984;
    float* st6 = dst + 2 * 2496;
    float* st7 = dst + 2 * 2752;
    float* st8 = dst + 2 * 2880;

    zerok<<<(5888 + 255) / 256, 256>>>(dst, 5888);
    zerok<<<1, 128>>>(dsg, 128);

    // L0: 7x7 reflect conv 3->16, 512x512, raw stats out
    conv7k<3, 16, 16, 32, 32, 2, 0, 0, 1, 3>
        <<<dim3(16, 16, 4), 256>>>(input, W[0], Bi[0], dA, nullptr, st0,
                                   0.f, 512, 512);

    // L1: 16->32 s2 -> 256x256 (IN of L0 fused)
    conv3s2k<16, 32, 128, 8, 8, 1, 1>
        <<<dim3(32, 32, 4), 128>>>(dA, W[1], Bi[1], dB, st0, st1,
                                   1.f / 262144.f, 512, 512);

    // L2: 32->64 s2 -> 128x128
    conv3s2k<32, 64, 128, 8, 8, 1, 1>
        <<<dim3(16, 16, 4), 128>>>(dB, W[2], Bi[2], dA, st1, st2,
                                   1.f / 65536.f, 256, 256);

    // L3: 64->128 s2 -> 64x64
    conv3s2k<64, 128, 256, 8, 4, 1, 1>
        <<<dim3(8, 8, 4), 256>>>(dA, W[3], Bi[3], dB, st2, st3,
                                 1.f / 16384.f, 128, 128);

    // L4: 128->256 s2 -> 32x32
    conv3s2k<128, 256, 128, 4, 4, 1, 1>
        <<<dim3(8, 8, 4), 128>>>(dB, W[4], Bi[4], dA, st3, st4,
                                 1.f / 4096.f, 64, 64);

    // L5: deconv 256->128 -> 64x64
    deconvk<256, 128, 256, 8, 4, 1, 1>
        <<<dim3(8, 8, 4), 256>>>(dA, W[5], Bi[5], dB, st4, st5,
                                 1.f / 1024.f, 32, 32);

    // L6: deconv 128->64 -> 128x128
    deconvk<128, 64, 128, 8, 8, 1, 1>
        <<<dim3(16, 16, 4), 128>>>(dB, W[6], Bi[6], dA, st5, st6,
                                   1.f / 4096.f, 64, 64);

    // L7: deconv 64->32 -> 256x256
    deconvk<64, 32, 128, 8, 8, 1, 1>
        <<<dim3(32, 32, 4), 128>>>(dA, W[7], Bi[7], dB, st6, st7,
                                   1.f / 16384.f, 128, 128);

    // L8: deconv 32->16 -> 512x512
    deconvk<32, 16, 128, 8, 16, 1, 1>
        <<<dim3(64, 64, 4), 128>>>(dB, W[8], Bi[8], dA, st7, st8,
                                   1.f / 65536.f, 256, 256);

    // L9: 7x7 reflect conv 16->3 + tanh (IN of L8 fused)
    conv7k<16, 3, 3, 32, 64, 4, 1, 1, 0, 2>
        <<<dim3(8, 16, 4), 256>>>(dA, W[9], Bi[9], dB, st8, nullptr,
                                  1.f / 262144.f, 512, 512);

    // Segment mean (seg_final folded into scatter)
    seg_accum<<<2048, 256>>>(dB, inst, dsg, 4, 262144);
    seg_scatter<<<4096, 256>>>(dsg, inst, out, 4, 262144);
}

// round 15
// speedup vs baseline: 1.4944x; 1.4944x over previous
#include <cuda_runtime.h>
#include <math.h>

// ---------------------------------------------------------------------------
// Scratch (device globals — no runtime allocation allowed)
// ---------------------------------------------------------------------------
#define BUF_ELEMS (4*16*512*512)   // 64 MB each
__device__ float g_bufA[BUF_ELEMS];
__device__ float g_bufB[BUF_ELEMS];
__device__ float g_stats[8192];    // per-layer (b,c) raw sum/sumsq
__device__ float g_seg[128];       // 32 segments x (3 channel sums + count)

__global__ void zerok(float* p, int n) {
    int i = blockIdx.x * blockDim.x + threadIdx.x;
    if (i < n) p[i] = 0.f;
}

__inline__ __device__ float warpSum(float v) {
    #pragma unroll
    for (int o = 16; o > 0; o >>= 1) v += __shfl_down_sync(0xffffffffu, v, o);
    return v;
}

__host__ __device__ constexpr int ilog2c(int n) {
    return n <= 1 ? 0 : 1 + ilog2c(n / 2);
}

// Build per-channel (mean, rstd) table in smem from raw sums (this block's b).
template<int CIN, int TPB>
__inline__ __device__ void buildMR(float* s_mr, const float* __restrict__ statsIn,
                                   int b, float inv_n, int t)
{
    for (int i = t; i < CIN; i += TPB) {
        float s  = statsIn[2 * (b * CIN + i)];
        float ss = statsIn[2 * (b * CIN + i) + 1];
        float m  = s * inv_n;
        float var = ss * inv_n - m * m;
        s_mr[2 * i]     = m;
        s_mr[2 * i + 1] = rsqrtf(fmaxf(var, 0.f) + 1e-5f);
    }
}

__inline__ __device__ float normMR(float v, const float* s_mr, int ci) {
    float y = (v - s_mr[2 * ci]) * s_mr[2 * ci + 1];
    return y > 0.f ? y : 0.f;
}

// ---------------------------------------------------------------------------
// 7x7 conv, reflect pad 3, stride 1 (layers 0 and 9). R5 geometry.
// ---------------------------------------------------------------------------
template<int CIN, int COUT, int COPT, int TILEY, int TILEX, int PXW,
         int ACT, int NORM, int STATS, int CB>
__global__ void __launch_bounds__(256) conv7k(
    const float* __restrict__ in, const float* __restrict__ w,
    const float* __restrict__ bias, float* __restrict__ out,
    const float* __restrict__ statsIn, float* statsOut, float inv_n,
    int H, int W)
{
    constexpr int CG  = COUT / COPT;
    constexpr int PXT = 256 / CG;
    constexpr int TX  = TILEX / PXW;
    constexpr int TY  = TILEY / 2;
    static_assert(TX * TY == PXT, "thread grid mismatch");
    constexpr int ITY = TILEY + 6, ITX = TILEX + 6;
    constexpr int STR = (ITX % 2 == 0) ? ITX + 1 : ITX;
    constexpr int NPP = 2 * PXW;
    constexpr int SS  = STATS ? 2 * COUT : 1;
    constexpr int SMR = NORM ? 2 * CIN : 1;

    __shared__ float wsm[COUT * CIN * 49];
    __shared__ float s_in[CB * ITY * STR];
    __shared__ float sstat[SS];
    __shared__ float s_mr[SMR];

    const int t   = threadIdx.x;
    const int cog = t / PXT;
    const int pt  = t % PXT;
    const int ptx = pt % TX, pty = pt / TX;
    const int b   = blockIdx.z;
    const int by  = blockIdx.y * TILEY, bx = blockIdx.x * TILEX;

    for (int i = t; i < COUT * CIN * 49; i += 256) wsm[i] = w[i];
    if (STATS) for (int i = t; i < 2 * COUT; i += 256) sstat[i] = 0.f;
    if (NORM)  buildMR<CIN, 256>(s_mr, statsIn, b, inv_n, t);

    float acc[COPT][NPP];
    #pragma unroll
    for (int o = 0; o < COPT; o++)
        #pragma unroll
        for (int p = 0; p < NPP; p++) acc[o][p] = 0.f;

    for (int ci0 = 0; ci0 < CIN; ci0 += CB) {
        __syncthreads();
        for (int i = t; i < CB * ITY * ITX; i += 256) {
            int ciL = i / (ITY * ITX);
            int rr  = i % (ITY * ITX);
            int r = rr / ITX, c = rr % ITX;
            int gy = by + r - 3; gy = gy < 0 ? -gy : gy; gy = gy >= H ? 2 * H - 2 - gy : gy;
            int gx = bx + c - 3; gx = gx < 0 ? -gx : gx; gx = gx >= W ? 2 * W - 2 - gx : gx;
            int ci = ci0 + ciL;
            float v = in[((b * CIN + ci) * H + gy) * W + gx];
            if (NORM) v = normMR(v, s_mr, ci);
            s_in[(ciL * ITY + r) * STR + c] = v;
        }
        __syncthreads();
        for (int ciL = 0; ciL < CB; ciL++) {
            const int ci = ci0 + ciL;
            #pragma unroll
            for (int ky = 0; ky < 7; ky++) {
                #pragma unroll
                for (int kx = 0; kx < 7; kx++) {
                    float wr[COPT];
                    #pragma unroll
                    for (int o = 0; o < COPT; o++)
                        wr[o] = wsm[((cog * COPT + o) * CIN + ci) * 49 + ky * 7 + kx];
                    #pragma unroll
                    for (int dy = 0; dy < 2; dy++) {
                        #pragma unroll
                        for (int dx = 0; dx < PXW; dx++) {
                            float v = s_in[(ciL * ITY + (2 * pty + dy + ky)) * STR
                                           + (PXW * ptx + dx + kx)];
                            #pragma unroll
                            for (int o = 0; o < COPT; o++)
                                acc[o][dy * PXW + dx] += v * wr[o];
                        }
                    }
                }
            }
        }
    }

    #pragma unroll
    for (int o = 0; o < COPT; o++) {
        int co = cog * COPT + o;
        float bb = bias[co];
        float s = 0.f, ssq = 0.f;
        #pragma unroll
        for (int p = 0; p < NPP; p++) {
            float v = acc[o][p] + bb;
            if (STATS) { s += v; ssq += v * v; }
            int py = p / PXW, pxc = p % PXW;
            int y = by + 2 * pty + py, x = bx + PXW * ptx + pxc;
            float ov = (ACT == 1) ? tanhf(v) : v;
            out[((b * COUT + co) * H + y) * W + x] = ov;
        }
        if (STATS) {
            s = warpSum(s); ssq = warpSum(ssq);
            if ((t & 31) == 0) {
                atomicAdd(&sstat[2 * co], s);
                atomicAdd(&sstat[2 * co + 1], ssq);
            }
        }
    }
    if (STATS) {
        __syncthreads();
        for (int i = t; i < 2 * COUT; i += 256)
            atomicAdd(&statsOut[2 * b * COUT + i], sstat[i]);
    }
}

// ---------------------------------------------------------------------------
// 3x3 stride-2 pad-1 conv, 2 co/thread, row-vectorized compute, per-ky
// weights. Weight smem CO-INNERMOST (R13 version, measured fastest):
// wsm[(ciL*9+k)*COUT + co]; warp cp values read stride-2 -> conflict-free.
// ---------------------------------------------------------------------------
template<int CIN, int COUT, int TPB, int TP, int CB, int NORM, int STATS>
__global__ void __launch_bounds__(TPB) conv3s2k(
    const float* __restrict__ in, const float* __restrict__ w,
    const float* __restrict__ bias, float* __restrict__ out,
    const float* __restrict__ statsIn, float* statsOut, float inv_n,
    int Hin, int Win)
{
    constexpr int CP   = COUT / 2;
    constexpr int G    = TPB / CP;
    constexpr int NPIX = TP * TP;
    constexpr int PX   = NPIX / G;
    static_assert(PX >= 1 && PX % TP == 0, "threads must own whole rows");
    constexpr int NROWS = PX / TP;
    constexpr int IW   = 2 * TP + 1;
    constexpr int SW   = ((IW + 3) / 4) * 4;   // 16B-aligned row stride
    constexpr int SS   = STATS ? 2 * COUT : 1;
    constexpr int SMR  = NORM ? 2 * CIN : 1;
    constexpr int LGC  = ilog2c(COUT);
    static_assert((1 << LGC) == COUT, "COUT must be pow2");

    __shared__ float wsm[CB * 9 * COUT];
    __shared__ __align__(16) float s_in[CB * IW * SW];
    __shared__ float sstat[SS];
    __shared__ float s_mr[SMR];

    const int t   = threadIdx.x;
    const int cp  = t % CP, g = t / CP;
    const int co0 = cp * 2;
    const int b   = blockIdx.z;
    const int oy0 = blockIdx.y * TP, ox0 = blockIdx.x * TP;
    const int Hout = Hin >> 1, Wout = Win >> 1;

    if (STATS) for (int i = t; i < 2 * COUT; i += TPB) sstat[i] = 0.f;
    if (NORM)  buildMR<CIN, TPB>(s_mr, statsIn, b, inv_n, t);

    float a0[PX], a1[PX];
    #pragma unroll
    for (int p = 0; p < PX; p++) { a0[p] = 0.f; a1[p] = 0.f; }

    for (int ci0 = 0; ci0 < CIN; ci0 += CB) {
        __syncthreads();
        // Weights: smem [kk][co] with kk = ciL*9 + k (co innermost).
        for (int i = t; i < CB * 9 * COUT; i += TPB) {
            int co  = i & (COUT - 1);
            int kk  = i >> LGC;
            int ciL = kk / 9, k = kk % 9;
            wsm[i] = w[(co * CIN + ci0 + ciL) * 9 + k];
        }
        for (int i = t; i < CB * IW * IW; i += TPB) {
            int ciL = i / (IW * IW);
            int rr  = i % (IW * IW);
            int r = rr / IW, c = rr % IW;
            int gy = 2 * oy0 - 1 + r, gx = 2 * ox0 - 1 + c;
            float v = 0.f;
            if (gy >= 0 && gy < Hin && gx >= 0 && gx < Win) {
                int ci = ci0 + ciL;
                v = in[((b * CIN + ci) * Hin + gy) * Win + gx];
                if (NORM) v = normMR(v, s_mr, ci);
            }
            s_in[(ciL * IW + r) * SW + c] = v;
        }
        __syncthreads();
        for (int ciL = 0; ciL < CB; ciL++) {
            const float* wbase = &wsm[(ciL * 9) * COUT + co0];
            #pragma unroll
            for (int rloc = 0; rloc < NROWS; rloc++) {
                const int py = g * NROWS + rloc;
                #pragma unroll
                for (int ky = 0; ky < 3; ky++) {
                    // per-ky weights, conflict-free (stride-2 across cp)
                    float w00 = wbase[(ky * 3 + 0) * COUT];
                    float w01 = wbase[(ky * 3 + 1) * COUT];
                    float w02 = wbase[(ky * 3 + 2) * COUT];
                    float w10 = wbase[(ky * 3 + 0) * COUT + 1];
                    float w11 = wbase[(ky * 3 + 1) * COUT + 1];
                    float w12 = wbase[(ky * 3 + 2) * COUT + 1];
                    const int iy = 2 * py + ky;
                    const float* rowp = &s_in[(ciL * IW + iy) * SW];
                    float rv[2 * TP + 1];
                    #pragma unroll
                    for (int j = 0; j < (2 * TP) / 4; j++) {
                        float4 q = *reinterpret_cast<const float4*>(rowp + 4 * j);
                        rv[4 * j]     = q.x;
                        rv[4 * j + 1] = q.y;
                        rv[4 * j + 2] = q.z;
                        rv[4 * j + 3] = q.w;
                    }
                    rv[2 * TP] = rowp[2 * TP];
                    #pragma unroll
                    for (int pxx = 0; pxx < TP; pxx++) {
                        float v0 = rv[2 * pxx];
                        float v1 = rv[2 * pxx + 1];
                        float v2 = rv[2 * pxx + 2];
                        a0[rloc * TP + pxx] += v0 * w00 + v1 * w01 + v2 * w02;
                        a1[rloc * TP + pxx] += v0 * w10 + v1 * w11 + v2 * w12;
                    }
                }
            }
        }
    }

    float b0v = bias[co0], b1v = bias[co0 + 1];
    float s0 = 0.f, ss0 = 0.f, s1 = 0.f, ss1 = 0.f;
    #pragma unroll
    for (int p = 0; p < PX; p++) {
        int pp = g * PX + p;
        int py = pp / TP, pxx = pp % TP;
        int oy = oy0 + py, ox = ox0 + pxx;
        float v0 = a0[p] + b0v, v1 = a1[p] + b1v;
        if (STATS) { s0 += v0; ss0 += v0 * v0; s1 += v1; ss1 += v1 * v1; }
        out[((b * COUT + co0) * Hout + oy) * Wout + ox]     = v0;
        out[((b * COUT + co0 + 1) * Hout + oy) * Wout + ox] = v1;
    }
    if (STATS) {
        atomicAdd(&sstat[2 * co0], s0);      atomicAdd(&sstat[2 * co0 + 1], ss0);
        atomicAdd(&sstat[2 * co0 + 2], s1);  atomicAdd(&sstat[2 * co0 + 3], ss1);
        __syncthreads();
        for (int i = t; i < 2 * COUT; i += TPB)
            atomicAdd(&statsOut[2 * b * COUT + i], sstat[i]);
    }
}

// ---------------------------------------------------------------------------
// ConvTranspose2d k=3 s=2 p=1 op=1, parity-specialized gather, 2 co/thread.
// R12 version (contiguous weight copy, original smem layout) — measured best.
// ---------------------------------------------------------------------------
template<int CIN, int COUT, int TPB, int TP, int CB, int NORM, int STATS>
__global__ void __launch_bounds__(TPB) deconvk(
    const float* __restrict__ in, const float* __restrict__ w,
    const float* __restrict__ bias, float* __restrict__ out,
    const float* __restrict__ statsIn, float* statsOut, float inv_n,
    int Hin, int Win)
{
    constexpr int CP   = COUT / 2;
    constexpr int G    = TPB / CP;
    constexpr int HT   = TP / 2;
    constexpr int QP   = (TP * TP) / (4 * G);
    constexpr int PX   = 4 * QP;
    static_assert(QP >= 1, "tile too small");
    constexpr int IH   = HT + 1;
    constexpr int SW   = IH + 1;
    constexpr int SS   = STATS ? 2 * COUT : 1;
    constexpr int SMR  = NORM ? 2 * CIN : 1;

    __shared__ float wsm[CB * COUT * 9];
    __shared__ float s_in[CB * IH * SW];
    __shared__ float sstat[SS];
    __shared__ float s_mr[SMR];

    const int t   = threadIdx.x;
    const int cp  = t % CP, g = t / CP;
    const int co0 = cp * 2;
    const int b   = blockIdx.z;
    const int oy0 = blockIdx.y * TP, ox0 = blockIdx.x * TP;
    const int iy0 = oy0 >> 1, ix0 = ox0 >> 1;
    const int Hout = Hin * 2, Wout = Win * 2;

    if (STATS) for (int i = t; i < 2 * COUT; i += TPB) sstat[i] = 0.f;
    if (NORM)  buildMR<CIN, TPB>(s_mr, statsIn, b, inv_n, t);

    float a0[PX], a1[PX];
    #pragma unroll
    for (int p = 0; p < PX; p++) { a0[p] = 0.f; a1[p] = 0.f; }

    for (int ci0 = 0; ci0 < CIN; ci0 += CB) {
        __syncthreads();
        for (int i = t; i < CB * COUT * 9; i += TPB)
            wsm[i] = w[ci0 * COUT * 9 + i];
        for (int i = t; i < CB * IH * IH; i += TPB) {
            int ciL = i / (IH * IH);
            int rr  = i % (IH * IH);
            int r = rr / IH, c = rr % IH;
            int gy = iy0 + r, gx = ix0 + c;
            float v = 0.f;
            if (gy < Hin && gx < Win) {
                int ci = ci0 + ciL;
                v = in[((b * CIN + ci) * Hin + gy) * Win + gx];
                if (NORM) v = normMR(v, s_mr, ci);
            }
            s_in[(ciL * IH + r) * SW + c] = v;
        }
        __syncthreads();
        for (int ciL = 0; ciL < CB; ciL++) {
            float w0[9], w1[9];
            #pragma unroll
            for (int k = 0; k < 9; k++) {
                w0[k] = wsm[(ciL * COUT + co0) * 9 + k];
                w1[k] = wsm[(ciL * COUT + co0 + 1) * 9 + k];
            }
            const int rowB = ciL * IH;
            #pragma unroll
            for (int p = 0; p < PX; p++) {
                const int dyp = (p >> 1) & 1;   // compile-time after unroll
                const int dxp = p & 1;
                const int q   = g * QP + (p >> 2);
                const int qy  = q / HT, qx = q % HT;
                if (dyp == 0 && dxp == 0) {
                    float v = s_in[(rowB + qy) * SW + qx];
                    a0[p] += v * w0[4];
                    a1[p] += v * w1[4];
                } else if (dyp == 0) {
                    float va = s_in[(rowB + qy) * SW + qx + 1];
                    float vb = s_in[(rowB + qy) * SW + qx];
                    a0[p] += va * w0[3] + vb * w0[5];
                    a1[p] += va * w1[3] + vb * w1[5];
                } else if (dxp == 0) {
                    float va = s_in[(rowB + qy + 1) * SW + qx];
                    float vb = s_in[(rowB + qy) * SW + qx];
                    a0[p] += va * w0[1] + vb * w0[7];
                    a1[p] += va * w1[1] + vb * w1[7];
                } else {
                    float vaa = s_in[(rowB + qy + 1) * SW + qx + 1];
                    float vab = s_in[(rowB + qy + 1) * SW + qx];
                    float vba = s_in[(rowB + qy) * SW + qx + 1];
                    float vbb = s_in[(rowB + qy) * SW + qx];
                    a0[p] += vaa * w0[0] + vab * w0[2] + vba * w0[6] + vbb * w0[8];
                    a1[p] += vaa * w1[0] + vab * w1[2] + vba * w1[6] + vbb * w1[8];
                }
            }
        }
    }

    float b0v = bias[co0], b1v = bias[co0 + 1];
    float s0 = 0.f, ss0 = 0.f, s1 = 0.f, ss1 = 0.f;
    #pragma unroll
    for (int p = 0; p < PX; p++) {
        const int dyp = (p >> 1) & 1;
        const int dxp = p & 1;
        const int q   = g * QP + (p >> 2);
        const int qy  = q / HT, qx = q % HT;
        int oy = oy0 + 2 * qy + dyp, ox = ox0 + 2 * qx + dxp;
        float v0 = a0[p] + b0v, v1 = a1[p] + b1v;
        if (STATS) { s0 += v0; ss0 += v0 * v0; s1 += v1; ss1 += v1 * v1; }
        out[((b * COUT + co0) * Hout + oy) * Wout + ox]     = v0;
        out[((b * COUT + co0 + 1) * Hout + oy) * Wout + ox] = v1;
    }
    if (STATS) {
        atomicAdd(&sstat[2 * co0], s0);      atomicAdd(&sstat[2 * co0 + 1], ss0);
        atomicAdd(&sstat[2 * co0 + 2], s1);  atomicAdd(&sstat[2 * co0 + 3], ss1);
        __syncthreads();
        for (int i = t; i < 2 * COUT; i += TPB)
            atomicAdd(&statsOut[2 * b * COUT + i], sstat[i]);
    }
}

// ---------------------------------------------------------------------------
// Global segment mean over all B*H*W pixels, 32 segments, C=3.
// ---------------------------------------------------------------------------
__global__ void __launch_bounds__(256) seg_accum(
    const float* __restrict__ x, const int* __restrict__ inst,
    float* sums, int B, int HW)
{
    __shared__ float ls[128];
    if (threadIdx.x < 128) ls[threadIdx.x] = 0.f;
    __syncthreads();
    int total = B * HW;
    for (int i = blockIdx.x * blockDim.x + threadIdx.x; i < total;
         i += gridDim.x * blockDim.x) {
        int b = i / HW, px = i % HW;
        int s = inst[(size_t)b * HW + px];
        atomicAdd(&ls[s * 4 + 3], 1.0f);
        #pragma unroll
        for (int c = 0; c < 3; c++)
            atomicAdd(&ls[s * 4 + c], x[((size_t)(b * 3 + c)) * HW + px]);
    }
    __syncthreads();
    if (threadIdx.x < 128) atomicAdd(&sums[threadIdx.x], ls[threadIdx.x]);
}

// Scatter with on-the-fly mean (folds seg_final).
__global__ void seg_scatter(const float* __restrict__ sums,
                            const int* __restrict__ inst,
                            float* __restrict__ out, int B, int HW)
{
    int total = B * HW;
    for (int i = blockIdx.x * blockDim.x + threadIdx.x; i < total;
         i += gridDim.x * blockDim.x) {
        int b = i / HW, px = i % HW;
        int s = inst[(size_t)b * HW + px];
        float inv = 1.0f / fmaxf(sums[s * 4 + 3], 1.0f);
        #pragma unroll
        for (int c = 0; c < 3; c++)
            out[((size_t)(b * 3 + c)) * HW + px] = sums[s * 4 + c] * inv;
    }
}

// ---------------------------------------------------------------------------
// Launch (identical to R12)
// ---------------------------------------------------------------------------
extern "C" void kernel_launch(void* const* d_in, const int* in_sizes, int n_in,
                              void* d_out, int out_size)
{
    (void)in_sizes; (void)n_in; (void)out_size;
    const float* input = (const float*)d_in[0];
    const int*   inst  = (const int*)d_in[1];
    const float* W[10]; const float* Bi[10];
    for (int i = 0; i < 10; i++) {
        W[i]  = (const float*)d_in[2 + 2 * i];
        Bi[i] = (const float*)d_in[3 + 2 * i];
    }
    float* out = (float*)d_out;

    float *dA, *dB, *dst, *dsg;
    cudaGetSymbolAddress((void**)&dA, g_bufA);
    cudaGetSymbolAddress((void**)&dB, g_bufB);
    cudaGetSymbolAddress((void**)&dst, g_stats);
    cudaGetSymbolAddress((void**)&dsg, g_seg);

    float* st0 = dst + 2 * 0;
    float* st1 = dst + 2 * 64;
    float* st2 = dst + 2 * 192;
    float* st3 = dst + 2 * 448;
    float* st4 = dst + 2 * 960;
    float* st5 = dst + 2 * 1984;
    float* st6 = dst + 2 * 2496;
    float* st7 = dst + 2 * 2752;
    float* st8 = dst + 2 * 2880;

    zerok<<<(5888 + 255) / 256, 256>>>(dst, 5888);
    zerok<<<1, 128>>>(dsg, 128);

    // L0: 7x7 reflect conv 3->16, 512x512, raw stats out
    conv7k<3, 16, 16, 32, 32, 2, 0, 0, 1, 3>
        <<<dim3(16, 16, 4), 256>>>(input, W[0], Bi[0], dA, nullptr, st0,
                                   0.f, 512, 512);

    // L1: 16->32 s2 -> 256x256 (IN of L0 fused)
    conv3s2k<16, 32, 128, 8, 8, 1, 1>
        <<<dim3(32, 32, 4), 128>>>(dA, W[1], Bi[1], dB, st0, st1,
                                   1.f / 262144.f, 512, 512);

    // L2: 32->64 s2 -> 128x128
    conv3s2k<32, 64, 128, 8, 8, 1, 1>
        <<<dim3(16, 16, 4), 128>>>(dB, W[2], Bi[2], dA, st1, st2,
                                   1.f / 65536.f, 256, 256);

    // L3: 64->128 s2 -> 64x64
    conv3s2k<64, 128, 256, 8, 4, 1, 1>
        <<<dim3(8, 8, 4), 256>>>(dA, W[3], Bi[3], dB, st2, st3,
                                 1.f / 16384.f, 128, 128);

    // L4: 128->256 s2 -> 32x32
    conv3s2k<128, 256, 128, 4, 4, 1, 1>
        <<<dim3(8, 8, 4), 128>>>(dB, W[4], Bi[4], dA, st3, st4,
                                 1.f / 4096.f, 64, 64);

    // L5: deconv 256->128 -> 64x64
    deconvk<256, 128, 256, 8, 4, 1, 1>
        <<<dim3(8, 8, 4), 256>>>(dA, W[5], Bi[5], dB, st4, st5,
                                 1.f / 1024.f, 32, 32);

    // L6: deconv 128->64 -> 128x128
    deconvk<128, 64, 128, 8, 8, 1, 1>
        <<<dim3(16, 16, 4), 128>>>(dB, W[6], Bi[6], dA, st5, st6,
                                   1.f / 4096.f, 64, 64);

    // L7: deconv 64->32 -> 256x256
    deconvk<64, 32, 128, 8, 8, 1, 1>
        <<<dim3(32, 32, 4), 128>>>(dA, W[7], Bi[7], dB, st6, st7,
                                   1.f / 16384.f, 128, 128);

    // L8: deconv 32->16 -> 512x512
    deconvk<32, 16, 128, 8, 16, 1, 1>
        <<<dim3(64, 64, 4), 128>>>(dB, W[8], Bi[8], dA, st7, st8,
                                   1.f / 65536.f, 256, 256);

    // L9: 7x7 reflect conv 16->3 + tanh (IN of L8 fused)
    conv7k<16, 3, 3, 32, 64, 4, 1, 1, 0, 2>
        <<<dim3(8, 16, 4), 256>>>(dA, W[9], Bi[9], dB, st8, nullptr,
                                  1.f / 262144.f, 512, 512);

    // Segment mean (seg_final folded into scatter)
    seg_accum<<<2048, 256>>>(dB, inst, dsg, 4, 262144);
    seg_scatter<<<4096, 256>>>(dsg, inst, out, 4, 262144);
}